// round 2
// baseline (speedup 1.0000x reference)
#include <cuda_runtime.h>
#include <cuda_bf16.h>
#include <stdint.h>

// Embedding_44994077393181
// out[b,t,:] = W_emb_tok[ argnz(X[b,t,:]) , : ] + X_emb_pos[t,:]
// X: (2,2048,32000) fp32 one-hot; W: (32000,1024) fp32; pos: (2048,1024) fp32
// One CTA per (b,t) row. Fine-grained (1024-float) early-exit scan minimizes
// expected X bytes read (~51.6% vs 50% theoretical floor), then fused
// gather + positional add. X is streamed with __ldcs to keep L2 for W/pos.

#define VOCAB   32000
#define EMB_DIM 1024
#define CTX     2048
#define NROWS   4096          // BATCH * CTX
#define THREADS 256
#define CHUNK   1024          // floats scanned per pass (THREADS * 4)
#define NPASS   32            // ceil(32000 / 1024)

__global__ __launch_bounds__(THREADS)
void embed_onehot_kernel(const float* __restrict__ X,
                         const float* __restrict__ W,
                         const float* __restrict__ pos,
                         float* __restrict__ out)
{
    const int row = blockIdx.x;            // 0..4095  (b = row / CTX, t = row % CTX)
    const int t   = row & (CTX - 1);
    const int tid = threadIdx.x;

    const float* xrow = X + (size_t)row * VOCAB;

    __shared__ int s_idx;

    // Fine-grained early-exit scan: 1024 floats (one float4/thread) per pass,
    // single fused barrier+reduction (__syncthreads_or) per pass.
    #pragma unroll 1
    for (int pass = 0; pass < NPASS; ++pass) {
        const int i = pass * CHUNK + (tid << 2);
        int found = -1;
        if (i < VOCAB) {
            const float4 v = __ldcs(reinterpret_cast<const float4*>(xrow + i));
            if (v.x != 0.0f) found = i;
            if (v.y != 0.0f) found = i + 1;
            if (v.z != 0.0f) found = i + 2;
            if (v.w != 0.0f) found = i + 3;
        }
        if (found >= 0) s_idx = found;     // exactly one nonzero per row -> no race
        if (__syncthreads_or(found >= 0)) break;
    }
    __syncthreads();                       // make s_idx visible on the break path

    const int idx = s_idx;

    // Fused gather + positional add: 1024 floats = 256 threads * float4.
    const float4 wv = __ldg(reinterpret_cast<const float4*>(W   + (size_t)idx * EMB_DIM) + tid);
    const float4 pv = __ldg(reinterpret_cast<const float4*>(pos + (size_t)t   * EMB_DIM) + tid);
    float4 o;
    o.x = wv.x + pv.x;
    o.y = wv.y + pv.y;
    o.z = wv.z + pv.z;
    o.w = wv.w + pv.w;
    reinterpret_cast<float4*>(out + (size_t)row * EMB_DIM)[tid] = o;
}

extern "C" void kernel_launch(void* const* d_in, const int* in_sizes, int n_in,
                              void* d_out, int out_size)
{
    const float* X   = (const float*)d_in[0];   // (2,2048,32000)
    const float* W   = (const float*)d_in[1];   // (32000,1024)
    const float* pos = (const float*)d_in[2];   // (2048,1024)
    float* out = (float*)d_out;                 // (2,2048,1024)

    embed_onehot_kernel<<<NROWS, THREADS>>>(X, W, pos, out);
}

// round 3
// speedup vs baseline: 1.2114x; 1.2114x over previous
#include <cuda_runtime.h>
#include <cuda_bf16.h>
#include <stdint.h>

// Embedding_44994077393181
// out[b,t,:] = W_emb_tok[ argnz(X[b,t,:]) , : ] + X_emb_pos[t,:]
// X: (2,2048,32000) fp32 one-hot; W: (32000,1024) fp32; pos: (2048,1024) fp32
// One CTA (128 threads) per (b,t) row. Early-exit scan in 2048-float chunks,
// 4 independent float4 loads per thread per pass (MLP=4), 16 CTAs/SM resident.
// Then fused gather + positional add. X streamed with __ldcs (zero reuse).

#define VOCAB   32000
#define EMB_DIM 1024
#define CTX     2048
#define NROWS   4096          // BATCH * CTX
#define THREADS 128
#define CHUNK   2048          // floats per pass = THREADS * 4 * 4
#define NPASS   16            // ceil(32000 / 2048)

__global__ __launch_bounds__(THREADS)
void embed_onehot_kernel(const float* __restrict__ X,
                         const float* __restrict__ W,
                         const float* __restrict__ pos,
                         float* __restrict__ out)
{
    const int row = blockIdx.x;            // 0..4095  (b = row / CTX, t = row % CTX)
    const int t   = row & (CTX - 1);
    const int tid = threadIdx.x;

    const float* xrow = X + (size_t)row * VOCAB;

    __shared__ int s_idx;

    // Early-exit scan: 2048 floats per pass, 4 independent float4 loads per
    // thread (keeps DRAM MLP high), one fused barrier+reduction per pass.
    #pragma unroll 1
    for (int pass = 0; pass < NPASS; ++pass) {
        const int base = pass * CHUNK;
        int found = -1;
        #pragma unroll
        for (int j = 0; j < 4; ++j) {
            const int i = base + ((j * THREADS + tid) << 2);
            if (i < VOCAB) {
                const float4 v = __ldcs(reinterpret_cast<const float4*>(xrow + i));
                if (v.x != 0.0f) found = i;
                if (v.y != 0.0f) found = i + 1;
                if (v.z != 0.0f) found = i + 2;
                if (v.w != 0.0f) found = i + 3;
            }
        }
        if (found >= 0) s_idx = found;     // exactly one nonzero per row -> no race
        if (__syncthreads_or(found >= 0)) break;
    }
    __syncthreads();                       // make s_idx visible on the break path

    const int idx = s_idx;

    // Fused gather + positional add: 1024 floats = 128 threads * 2 float4.
    const float4* wrow = reinterpret_cast<const float4*>(W   + (size_t)idx * EMB_DIM);
    const float4* prow = reinterpret_cast<const float4*>(pos + (size_t)t   * EMB_DIM);
    float4*       orow = reinterpret_cast<float4*>(out + (size_t)row * EMB_DIM);

    #pragma unroll
    for (int j = 0; j < 2; ++j) {
        const int c = j * THREADS + tid;
        const float4 wv = __ldg(wrow + c);
        const float4 pv = __ldg(prow + c);
        float4 o;
        o.x = wv.x + pv.x;
        o.y = wv.y + pv.y;
        o.z = wv.z + pv.z;
        o.w = wv.w + pv.w;
        orow[c] = o;
    }
}

extern "C" void kernel_launch(void* const* d_in, const int* in_sizes, int n_in,
                              void* d_out, int out_size)
{
    const float* X   = (const float*)d_in[0];   // (2,2048,32000)
    const float* W   = (const float*)d_in[1];   // (32000,1024)
    const float* pos = (const float*)d_in[2];   // (2048,1024)
    float* out = (float*)d_out;                 // (2,2048,1024)

    embed_onehot_kernel<<<NROWS, THREADS>>>(X, W, pos, out);
}